// round 5
// baseline (speedup 1.0000x reference)
#include <cuda_runtime.h>

// Problem shape (fixed): x_hr (16,3,512,512) f32, w1 (3,9) f32.
#define BB 16
#define HH 512
#define WW 512
#define HW (HH*WW)
#define NPIX (BB*HW)
#define NT 512

// Per-pixel scratch maps (__device__ globals are allowed).
__device__ float2 g_uv[NPIX];   // (sum_c x, sum_c x^2)
__device__ float2 g_P1[NPIX];   // cumulative affine after stage 1: F1 = P.x*x + P.y
__device__ float2 g_P2[NPIX];   // cumulative affine after stage 2
__device__ float2 g_AB[NPIX];   // per-stage (A,b) intermediate
__constant__ float cw[27];      // 1x1 conv weights (3x9)

// ---------------- fused stage-1 kernel (R=1, tiny halo) ----------------
template <int R, int T>
__global__ void __launch_bounds__(NT, 3) stage1_kernel(const float* __restrict__ x) {
    constexpr int K  = 2 * R + 1;
    constexpr int E1 = T + 2 * R;
    constexpr int E2 = T + 4 * R;
    constexpr int SP = E2 + 1;     // odd float2 stride (column access in H passes)
    constexpr int HP = E1 + 1;
    constexpr float EPS = 0.16f;

    constexpr int NS1 = NT / E2, LS1 = (E1 + NS1 - 1) / NS1;
    constexpr int NV1 = NT / E1, LV1 = (E1 + NV1 - 1) / NV1;
    constexpr int NS2 = NT / E1, LS2 = (T + NS2 - 1) / NS2;
    constexpr int NV2 = NT / T,  LV2 = (T + NV2 - 1) / NV2;

    extern __shared__ float2 sm2[];
    float2* SS = sm2;
    float2* Hs = SS + E2 * SP;
    float*  ry = (float*)(Hs + E2 * HP);

    const int tid = threadIdx.x;
    const int gx0 = blockIdx.x * T, gy0 = blockIdx.y * T;
    const int b = blockIdx.z, gb = b * HW;

    if (tid < E1) {
        int gy = gy0 - R + tid;
        float r = 0.f;
        if ((unsigned)gy < (unsigned)HH)
            r = __frcp_rn((float)(min(gy + R, HH - 1) - max(gy - R, 0) + 1));
        ry[tid] = r;
    }

    for (int idx = tid; idx < E2 * E2; idx += NT) {
        int iy = idx / E2, ix = idx - iy * E2;
        int gy = gy0 - 2 * R + iy, gx = gx0 - 2 * R + ix;
        float2 s = make_float2(0.f, 0.f);
        if ((unsigned)gy < (unsigned)HH && (unsigned)gx < (unsigned)WW) {
            const float* xb = x + (size_t)b * 3 * HW + gy * WW + gx;
            float x0 = xb[0], x1 = xb[HW], x2 = xb[2 * HW];
            s.x = x0 + x1 + x2;
            s.y = x0 * x0 + x1 * x1 + x2 * x2;
            if (iy >= 2 * R && iy < 2 * R + T && ix >= 2 * R && ix < 2 * R + T)
                g_uv[gb + gy * WW + gx] = s;
        }
        SS[iy * SP + ix] = s;
    }
    __syncthreads();

    for (int item = tid; item < E2 * NS1; item += NT) {
        int r = item % E2, seg = item / E2;
        int c0 = seg * LS1, c1 = min(E1, c0 + LS1);
        if (c0 >= c1) continue;
        const float2* p = SS + r * SP;
        float2* o = Hs + r * HP;
        float ax = 0.f, ay = 0.f;
#pragma unroll
        for (int j = 0; j < K; ++j) { float2 v = p[c0 + j]; ax += v.x; ay += v.y; }
        o[c0] = make_float2(ax, ay);
        for (int c = c0 + 1; c < c1; ++c) {
            float2 vi = p[c + 2 * R], vo = p[c - 1];
            ax += vi.x - vo.x; ay += vi.y - vo.y;
            o[c] = make_float2(ax, ay);
        }
    }
    __syncthreads();

    for (int item = tid; item < E1 * NV1; item += NT) {
        int c = item % E1, seg = item / E1;
        int r0 = seg * LV1, re = min(E1, r0 + LV1);
        if (r0 >= re) continue;
        int gx = gx0 - R + c;
        float rx = 0.f;
        if ((unsigned)gx < (unsigned)WW)
            rx = __frcp_rn(3.f * (float)(min(gx + R, WW - 1) - max(gx - R, 0) + 1));
        float a1 = 0.f, a2 = 0.f;
#pragma unroll
        for (int j = 0; j < K; ++j) { float2 v = Hs[(r0 + j) * HP + c]; a1 += v.x; a2 += v.y; }
        for (int i = r0;;) {
            float inv = ry[i] * rx;
            float m = a1 * inv, q = a2 * inv;
            float var = fmaf(-m, m, q);
            float rr = __frcp_rn(var + EPS);
            SS[i * SP + c] = make_float2(var * rr, m * (EPS * rr));
            if (++i >= re) break;
            float2 vi = Hs[(i - 1 + K) * HP + c], vo = Hs[(i - 1) * HP + c];
            a1 += vi.x - vo.x; a2 += vi.y - vo.y;
        }
    }
    __syncthreads();

    for (int item = tid; item < E1 * NS2; item += NT) {
        int r = item % E1, seg = item / E1;
        int c0 = seg * LS2, c1 = min(T, c0 + LS2);
        if (c0 >= c1) continue;
        const float2* p = SS + r * SP;
        float2* o = Hs + r * HP;
        float ax = 0.f, ay = 0.f;
#pragma unroll
        for (int j = 0; j < K; ++j) { float2 v = p[c0 + j]; ax += v.x; ay += v.y; }
        o[c0] = make_float2(ax, ay);
        for (int c = c0 + 1; c < c1; ++c) {
            float2 vi = p[c + 2 * R], vo = p[c - 1];
            ax += vi.x - vo.x; ay += vi.y - vo.y;
            o[c] = make_float2(ax, ay);
        }
    }
    __syncthreads();

    for (int item = tid; item < T * NV2; item += NT) {
        int c = item % T, seg = item / T;
        int r0 = seg * LV2, re = min(T, r0 + LV2);
        if (r0 >= re) continue;
        int gx = gx0 + c;
        float a1 = 0.f, a2 = 0.f;
#pragma unroll
        for (int j = 0; j < K; ++j) { float2 v = Hs[(r0 + j) * HP + c]; a1 += v.x; a2 += v.y; }
        for (int i = r0;;) {
            int gy = gy0 + i;
            g_P1[gb + gy * WW + gx] = make_float2(3.f * a1, 3.f * a2);
            if (++i >= re) break;
            float2 vi = Hs[(i - 1 + K) * HP + c], vo = Hs[(i - 1) * HP + c];
            a1 += vi.x - vo.x; a2 += vi.y - vo.y;
        }
    }
}

// ---------------- split kernels for stages 2 & 3 ----------------
// PHASE 0 (AB):  pointwise channel sums -> box1 -> (A,b) -> g_AB
// PHASE 1 (OUT): g_AB -> box2 -> affine update (stage2) or final epilogue (stage3)
template <int R, int PHASE, int STG, int T, int MINB>
__global__ void __launch_bounds__(NT, MINB) split_kernel(const float* __restrict__ x,
                                                         float* __restrict__ out) {
    constexpr int K = 2 * R + 1;
    constexpr int E = T + 2 * R;
    constexpr int SPD = E + 1;     // odd float2 stride
    constexpr int HPD = T + 1;
    constexpr float EPS = (STG == 2) ? 0.04f : 0.01f;

    constexpr int NSH = NT / E, LSH = (T + NSH - 1) / NSH;
    constexpr int NSV = 8,      LSV = (T + NSV - 1) / NSV;

    extern __shared__ float2 sm2[];
    float2* SS = sm2;              // E x SPD
    float2* Hs = SS + E * SPD;     // E x HPD
    float*  ry = (float*)(Hs + E * HPD);   // T row factors (PHASE 0)

    const int tid = threadIdx.x;
    const int gx0 = blockIdx.x * T, gy0 = blockIdx.y * T;
    const int b = blockIdx.z, gb = b * HW;

    if (PHASE == 0 && tid < T) {
        int gy = gy0 + tid;
        float r = 0.f;
        if ((unsigned)gy < (unsigned)HH)
            r = __frcp_rn((float)(min(gy + R, HH - 1) - max(gy - R, 0) + 1));
        ry[tid] = r;
    }

    // load E x E (zero outside image)
    for (int idx = tid; idx < E * E; idx += NT) {
        int iy = idx / E, ix = idx - iy * E;
        int gy = gy0 - R + iy, gx = gx0 - R + ix;
        float2 s = make_float2(0.f, 0.f);
        if ((unsigned)gy < (unsigned)HH && (unsigned)gx < (unsigned)WW) {
            int g = gb + gy * WW + gx;
            if (PHASE == 0) {
                float2 uv = g_uv[g];
                float2 P  = (STG == 2) ? g_P1[g] : g_P2[g];
                s.x = fmaf(P.x, uv.x, 3.f * P.y);
                s.y = fmaf(P.x * P.x, uv.y, fmaf(2.f * P.x * P.y, uv.x, 3.f * P.y * P.y));
            } else {
                s = g_AB[g];
            }
        }
        SS[iy * SPD + ix] = s;
    }
    __syncthreads();

    // horizontal box: Hs[r][c] = sum_{j=c..c+2R} SS[r][j], r<E, c<T
    for (int item = tid; item < E * NSH; item += NT) {
        int r = item % E, seg = item / E;
        int c0 = seg * LSH, c1 = min(T, c0 + LSH);
        if (c0 >= c1) continue;
        const float2* p = SS + r * SPD;
        float2* o = Hs + r * HPD;
        float ax = 0.f, ay = 0.f;
#pragma unroll
        for (int j = 0; j < K; ++j) { float2 v = p[c0 + j]; ax += v.x; ay += v.y; }
        o[c0] = make_float2(ax, ay);
        for (int c = c0 + 1; c < c1; ++c) {
            float2 vi = p[c + 2 * R], vo = p[c - 1];
            ax += vi.x - vo.x; ay += vi.y - vo.y;
            o[c] = make_float2(ax, ay);
        }
    }
    __syncthreads();

    // vertical box + transform, T x T outputs
    for (int item = tid; item < T * NSV; item += NT) {
        int c = item % T, seg = item / T;
        int r0 = seg * LSV, re = min(T, r0 + LSV);
        if (r0 >= re) continue;
        int gx = gx0 + c;
        float rx = 0.f;
        if (PHASE == 0 && (unsigned)gx < (unsigned)WW)
            rx = __frcp_rn(3.f * (float)(min(gx + R, WW - 1) - max(gx - R, 0) + 1));
        float a1 = 0.f, a2 = 0.f;
#pragma unroll
        for (int j = 0; j < K; ++j) { float2 v = Hs[(r0 + j) * HPD + c]; a1 += v.x; a2 += v.y; }
        for (int i = r0;;) {
            int gy = gy0 + i;
            if (gy < HH && gx < WW) {
                int g = gb + gy * WW + gx;
                if (PHASE == 0) {
                    float inv = ry[i] * rx;
                    float m = a1 * inv, q = a2 * inv;
                    float var = fmaf(-m, m, q);
                    float rr = __frcp_rn(var + EPS);
                    g_AB[g] = make_float2(var * rr, m * (EPS * rr));
                } else {
                    float a = 3.f * a1, cc = 3.f * a2;
                    if (STG == 2) {
                        float2 p = g_P1[g];
                        g_P2[g] = make_float2(a * p.x, fmaf(a, p.y, cc));
                    } else {
                        float2 p1 = g_P1[g], p2 = g_P2[g];
                        float A3 = a * p2.x, C3 = fmaf(a, p2.y, cc);
                        float al0 = 1.f - p1.x, be0 = -p1.y;
                        float al1 = p1.x - p2.x, be1 = p1.y - p2.y;
                        float al2 = p2.x - A3,   be2 = p2.y - C3;
                        const float* xp = x + (size_t)b * 3 * HW + gy * WW + gx;
                        float x0 = xp[0], x1 = xp[HW], x2 = xp[2 * HW];
                        float d0 = fmaf(al0, x0, be0), d1 = fmaf(al0, x1, be0), d2 = fmaf(al0, x2, be0);
                        float d3 = fmaf(al1, x0, be1), d4 = fmaf(al1, x1, be1), d5 = fmaf(al1, x2, be1);
                        float d6 = fmaf(al2, x0, be2), d7 = fmaf(al2, x1, be2), d8 = fmaf(al2, x2, be2);
#pragma unroll
                        for (int o = 0; o < 3; ++o) {
                            float acc =      cw[o * 9 + 0] * d0;
                            acc = fmaf(cw[o * 9 + 1], d1, acc);
                            acc = fmaf(cw[o * 9 + 2], d2, acc);
                            acc = fmaf(cw[o * 9 + 3], d3, acc);
                            acc = fmaf(cw[o * 9 + 4], d4, acc);
                            acc = fmaf(cw[o * 9 + 5], d5, acc);
                            acc = fmaf(cw[o * 9 + 6], d6, acc);
                            acc = fmaf(cw[o * 9 + 7], d7, acc);
                            acc = fmaf(cw[o * 9 + 8], d8, acc);
                            out[(size_t)(b * 3 + o) * HW + (size_t)gy * WW + gx] = acc;
                        }
                    }
                }
            }
            if (++i >= re) break;
            float2 vi = Hs[(i - 1 + K) * HPD + c], vo = Hs[(i - 1) * HPD + c];
            a1 += vi.x - vo.x; a2 += vi.y - vo.y;
        }
    }
}

static constexpr int fused_smem(int R, int T) {
    int E1 = T + 2 * R, E2 = T + 4 * R;
    return (E2 * (E2 + 1) + E2 * (E1 + 1)) * 8 + E1 * 4;
}
static constexpr int split_smem(int R, int T) {
    int E = T + 2 * R;
    return (E * (E + 1) + E * (T + 1)) * 8 + T * 4;
}

extern "C" void kernel_launch(void* const* d_in, const int* in_sizes, int n_in,
                              void* d_out, int out_size) {
    const float* x  = (const float*)d_in[0];
    const float* wg = (const float*)d_in[1];
    float* out = (float*)d_out;

    cudaMemcpyToSymbolAsync(cw, wg, 27 * sizeof(float), 0, cudaMemcpyDeviceToDevice);

    constexpr int SB1  = fused_smem(1, 64);   // ~74.2 KB -> 3 blocks/SM
    constexpr int SB2  = split_smem(3, 64);   // ~76.4 KB -> 3 blocks/SM
    constexpr int SB3  = split_smem(7, 48);   // ~55.7 KB -> 4 blocks/SM
    cudaFuncSetAttribute((const void*)stage1_kernel<1, 64>,        cudaFuncAttributeMaxDynamicSharedMemorySize, SB1);
    cudaFuncSetAttribute((const void*)split_kernel<3, 0, 2, 64, 3>, cudaFuncAttributeMaxDynamicSharedMemorySize, SB2);
    cudaFuncSetAttribute((const void*)split_kernel<3, 1, 2, 64, 3>, cudaFuncAttributeMaxDynamicSharedMemorySize, SB2);
    cudaFuncSetAttribute((const void*)split_kernel<7, 0, 3, 48, 4>, cudaFuncAttributeMaxDynamicSharedMemorySize, SB3);
    cudaFuncSetAttribute((const void*)split_kernel<7, 1, 3, 48, 3>, cudaFuncAttributeMaxDynamicSharedMemorySize, SB3);

    dim3 g64(WW / 64, HH / 64, BB);
    dim3 g48((WW + 47) / 48, (HH + 47) / 48, BB);

    stage1_kernel<1, 64><<<g64, NT, SB1>>>(x);
    split_kernel<3, 0, 2, 64, 3><<<g64, NT, SB2>>>(x, out);
    split_kernel<3, 1, 2, 64, 3><<<g64, NT, SB2>>>(x, out);
    split_kernel<7, 0, 3, 48, 4><<<g48, NT, SB3>>>(x, out);
    split_kernel<7, 1, 3, 48, 3><<<g48, NT, SB3>>>(x, out);
}

// round 6
// speedup vs baseline: 1.0598x; 1.0598x over previous
#include <cuda_runtime.h>

// Problem shape (fixed): x_hr (16,3,512,512) f32, w1 (3,9) f32.
#define BB 16
#define HH 512
#define WW 512
#define HW (HH*WW)
#define NPIX (BB*HW)
#define NT 512

// Per-pixel scratch maps (__device__ globals are allowed).
__device__ float2 g_uv[NPIX];   // (sum_c x, sum_c x^2)
__device__ float2 g_P1[NPIX];   // cumulative affine after stage 1: F1 = P.x*x + P.y
__device__ float2 g_P2[NPIX];   // cumulative affine after stage 2
__constant__ float cw[27];      // 1x1 conv weights (3x9)

// Channel-sum evaluator: s = (sum_c F, sum_c F^2) of the stage's input image at
// (gy,gx), computed pointwise from uv + cumulative affine. Zero outside image.
// Stage 1 also produces uv from x and (optionally) persists it.
template <int STAGE>
__device__ __forceinline__ float2 s_eval(const float* __restrict__ x, int b,
                                         int gy, int gx, bool vx, bool wr,
                                         int gy0) {
    if (!vx || (unsigned)gy >= (unsigned)HH) return make_float2(0.f, 0.f);
    int g = b * HW + gy * WW + gx;
    if (STAGE == 1) {
        const float* xp = x + (size_t)b * 3 * HW + gy * WW + gx;
        float x0 = xp[0], x1 = xp[HW], x2 = xp[2 * HW];
        float2 s = make_float2(x0 + x1 + x2, x0 * x0 + x1 * x1 + x2 * x2);
        if (wr && gy >= gy0 && gy < gy0 + 64) g_uv[g] = s;   // interior persist
        return s;
    } else {
        float2 uv = g_uv[g];
        float2 P  = (STAGE == 2) ? g_P1[g] : g_P2[g];
        return make_float2(fmaf(P.x, uv.x, 3.f * P.y),
                           fmaf(P.x * P.x, uv.y,
                                fmaf(2.f * P.x * P.y, uv.x, 3.f * P.y * P.y)));
    }
}

// One guided-filter stage: 4 phases, no raw-tile smem staging.
//  P1: vertical K-box of s, computed straight off global loads  -> V1 (smem)
//  P2: horizontal K-box + pointwise (A,b)                       -> AB (smem)
//  P3: horizontal K-box of AB                                   -> G (aliases V1)
//  P4: vertical K-box of G + epilogue, coalesced global writes
template <int R, int STAGE, int T, int MINB>
__global__ void __launch_bounds__(NT, MINB) gf_kernel(const float* __restrict__ x,
                                                      float* __restrict__ out) {
    constexpr int K   = 2 * R + 1;
    constexpr int H1R = T + 2 * R;   // rows where (A,b) needed
    constexpr int W2  = T + 2 * R;   // cols where (A,b) needed
    constexpr int W1  = T + 4 * R;   // cols where V1 needed
    constexpr int P1W = W1 + 1;      // odd float2 strides -> conflict-free
    constexpr int ABW = W2 + 1;
    constexpr int GW  = T + 1;
    constexpr float EPS = (STAGE == 1) ? 0.16f : ((STAGE == 2) ? 0.04f : 0.01f);

    constexpr int NSEG1 = NT / W1,  LR1 = (H1R + NSEG1 - 1) / NSEG1;
    constexpr int NSEG2 = NT / H1R, LC2 = (W2 + NSEG2 - 1) / NSEG2;
    constexpr int NSEG3 = NT / H1R, LC3 = (T + NSEG3 - 1) / NSEG3;
    constexpr int NSEG4 = NT / T,   LR4 = (T + NSEG4 - 1) / NSEG4;

    extern __shared__ float2 sm2[];
    float2* V1 = sm2;                    // H1R x P1W
    float2* AB = V1 + H1R * P1W;         // H1R x ABW
    float2* G  = V1;                     // H1R x GW (aliases dead V1 in P3/P4)
    float*  rx = (float*)(AB + H1R * ABW);   // W2 col border factors (1/cx, 0 outside)
    float*  ry = rx + W2;                    // H1R row border factors (1/(3cy), 0 outside)

    const int tid = threadIdx.x;
    const int gx0 = blockIdx.x * T, gy0 = blockIdx.y * T;
    const int b = blockIdx.z, gb = b * HW;

    // border-factor tables (read first in P2; covered by the P1->P2 barrier)
    if (tid < W2) {
        int gx = gx0 - R + tid;
        float v = 0.f;
        if ((unsigned)gx < (unsigned)WW)
            v = __frcp_rn((float)(min(gx + R, WW - 1) - max(gx - R, 0) + 1));
        rx[tid] = v;
    }
    int t2 = tid - 128;
    if (t2 >= 0 && t2 < H1R) {
        int gy = gy0 - R + t2;
        float v = 0.f;
        if ((unsigned)gy < (unsigned)HH)
            v = __frcp_rn(3.f * (float)(min(gy + R, HH - 1) - max(gy - R, 0) + 1));
        ry[t2] = v;
    }

    // ---- P1: vertical box of s directly from global ----
    for (int item = tid; item < W1 * NSEG1; item += NT) {
        int c = item % W1, seg = item / W1;
        int r0 = seg * LR1, re = min(H1R, r0 + LR1);
        if (r0 >= re) continue;
        int gx = gx0 - 2 * R + c;
        bool vx = (unsigned)gx < (unsigned)WW;
        bool wr = vx && c >= 2 * R && c < 2 * R + T;   // stage-1 uv persist gate
        int ybase = gy0 - 2 * R + r0;
        float a1 = 0.f, a2 = 0.f;
#pragma unroll
        for (int j = 0; j < K; ++j) {
            float2 s = s_eval<STAGE>(x, b, ybase + j, gx, vx, wr, gy0);
            a1 += s.x; a2 += s.y;
        }
        for (int r = r0;;) {
            V1[r * P1W + c] = make_float2(a1, a2);
            if (++r >= re) break;
            float2 sa = s_eval<STAGE>(x, b, ybase + (r - r0) + K - 1, gx, vx, wr, gy0);
            float2 sb = s_eval<STAGE>(x, b, ybase + (r - r0) - 1,     gx, vx, false, gy0);
            a1 += sa.x - sb.x; a2 += sa.y - sb.y;
        }
    }
    __syncthreads();

    // ---- P2: horizontal box + pointwise (A,b) ----
    for (int item = tid; item < H1R * NSEG2; item += NT) {
        int r = item % H1R, seg = item / H1R;
        int c0 = seg * LC2, ce = min(W2, c0 + LC2);
        if (c0 >= ce) continue;
        float ryv = ry[r];
        const float2* vrow = V1 + r * P1W;
        float2* arow = AB + r * ABW;
        float a1 = 0.f, a2 = 0.f;
#pragma unroll
        for (int j = 0; j < K; ++j) { float2 v = vrow[c0 + j]; a1 += v.x; a2 += v.y; }
        for (int c = c0;;) {
            float inv = ryv * rx[c];         // 1/Nc (0 outside image -> A=b=0)
            float m = a1 * inv, q = a2 * inv;
            float var = fmaf(-m, m, q);
            float rr = __frcp_rn(var + EPS);
            arow[c] = make_float2(var * rr, m * (EPS * rr));
            if (++c >= ce) break;
            float2 vi = vrow[c - 1 + K], vo = vrow[c - 1];
            a1 += vi.x - vo.x; a2 += vi.y - vo.y;
        }
    }
    __syncthreads();

    // ---- P3: horizontal box of (A,b) -> G (aliases V1) ----
    for (int item = tid; item < H1R * NSEG3; item += NT) {
        int r = item % H1R, seg = item / H1R;
        int c0 = seg * LC3, ce = min(T, c0 + LC3);
        if (c0 >= ce) continue;
        const float2* arow = AB + r * ABW;
        float2* grow = G + r * GW;
        float a1 = 0.f, a2 = 0.f;
#pragma unroll
        for (int j = 0; j < K; ++j) { float2 v = arow[c0 + j]; a1 += v.x; a2 += v.y; }
        for (int c = c0;;) {
            grow[c] = make_float2(a1, a2);
            if (++c >= ce) break;
            float2 vi = arow[c - 1 + K], vo = arow[c - 1];
            a1 += vi.x - vo.x; a2 += vi.y - vo.y;
        }
    }
    __syncthreads();

    // ---- P4: vertical box of G + epilogue (coalesced writes) ----
    for (int item = tid; item < T * NSEG4; item += NT) {
        int c = item % T, seg = item / T;
        int r0 = seg * LR4, re = min(T, r0 + LR4);
        if (r0 >= re) continue;
        int gx = gx0 + c;
        float a1 = 0.f, a2 = 0.f;
#pragma unroll
        for (int j = 0; j < K; ++j) { float2 v = G[(r0 + j) * GW + c]; a1 += v.x; a2 += v.y; }
        for (int r = r0;;) {
            int gy = gy0 + r;
            if (gy < HH && gx < WW) {
                int g = gb + gy * WW + gx;
                float a = 3.f * a1, cc = 3.f * a2;   // mean_A/mean_b = C*box, C=3
                if (STAGE == 1) {
                    g_P1[g] = make_float2(a, cc);
                } else if (STAGE == 2) {
                    float2 p = g_P1[g];
                    g_P2[g] = make_float2(a * p.x, fmaf(a, p.y, cc));
                } else {
                    float2 p1 = g_P1[g], p2 = g_P2[g];
                    float A3 = a * p2.x, C3 = fmaf(a, p2.y, cc);
                    float al0 = 1.f - p1.x, be0 = -p1.y;
                    float al1 = p1.x - p2.x, be1 = p1.y - p2.y;
                    float al2 = p2.x - A3,   be2 = p2.y - C3;
                    const float* xp = x + (size_t)b * 3 * HW + gy * WW + gx;
                    float x0 = xp[0], x1 = xp[HW], x2 = xp[2 * HW];
                    float d0 = fmaf(al0, x0, be0), d1 = fmaf(al0, x1, be0), d2 = fmaf(al0, x2, be0);
                    float d3 = fmaf(al1, x0, be1), d4 = fmaf(al1, x1, be1), d5 = fmaf(al1, x2, be1);
                    float d6 = fmaf(al2, x0, be2), d7 = fmaf(al2, x1, be2), d8 = fmaf(al2, x2, be2);
#pragma unroll
                    for (int o = 0; o < 3; ++o) {
                        float acc =      cw[o * 9 + 0] * d0;
                        acc = fmaf(cw[o * 9 + 1], d1, acc);
                        acc = fmaf(cw[o * 9 + 2], d2, acc);
                        acc = fmaf(cw[o * 9 + 3], d3, acc);
                        acc = fmaf(cw[o * 9 + 4], d4, acc);
                        acc = fmaf(cw[o * 9 + 5], d5, acc);
                        acc = fmaf(cw[o * 9 + 6], d6, acc);
                        acc = fmaf(cw[o * 9 + 7], d7, acc);
                        acc = fmaf(cw[o * 9 + 8], d8, acc);
                        out[(size_t)(b * 3 + o) * HW + (size_t)gy * WW + gx] = acc;
                    }
                }
            }
            if (++r >= re) break;
            float2 vi = G[(r - 1 + K) * GW + c], vo = G[(r - 1) * GW + c];
            a1 += vi.x - vo.x; a2 += vi.y - vo.y;
        }
    }
}

static constexpr int gf_smem(int R, int T) {
    int H1R = T + 2 * R, W2 = T + 2 * R, W1 = T + 4 * R;
    return (H1R * (W1 + 1) + H1R * (W2 + 1)) * 8 + (W2 + H1R) * 4;
}

extern "C" void kernel_launch(void* const* d_in, const int* in_sizes, int n_in,
                              void* d_out, int out_size) {
    const float* x  = (const float*)d_in[0];
    const float* wg = (const float*)d_in[1];
    float* out = (float*)d_out;

    cudaMemcpyToSymbolAsync(cw, wg, 27 * sizeof(float), 0, cudaMemcpyDeviceToDevice);

    constexpr int SB1 = gf_smem(1, 64);   // ~72.3 KB -> 3 blocks/SM
    constexpr int SB2 = gf_smem(3, 64);   // ~83.4 KB -> 2 blocks/SM
    constexpr int SB3 = gf_smem(7, 48);   // ~69.9 KB -> 3 blocks/SM
    cudaFuncSetAttribute((const void*)gf_kernel<1, 1, 64, 3>, cudaFuncAttributeMaxDynamicSharedMemorySize, SB1);
    cudaFuncSetAttribute((const void*)gf_kernel<3, 2, 64, 2>, cudaFuncAttributeMaxDynamicSharedMemorySize, SB2);
    cudaFuncSetAttribute((const void*)gf_kernel<7, 3, 48, 3>, cudaFuncAttributeMaxDynamicSharedMemorySize, SB3);

    dim3 g64(WW / 64, HH / 64, BB);
    dim3 g48((WW + 47) / 48, (HH + 47) / 48, BB);

    gf_kernel<1, 1, 64, 3><<<g64, NT, SB1>>>(x, out);
    gf_kernel<3, 2, 64, 2><<<g64, NT, SB2>>>(x, out);
    gf_kernel<7, 3, 48, 3><<<g48, NT, SB3>>>(x, out);
}